// round 7
// baseline (speedup 1.0000x reference)
#include <cuda_runtime.h>
#include <math.h>

// BernsteinNetwork: N=32768, D=8, ORDER=24, P=32
#define NSAMP 32768
#define PPERM 32

typedef unsigned long long u64;

// ---------------- scratch (no device allocation allowed) ----------------
__device__ float g_sc2[25];
__device__ __align__(16) u64 g_W [PPERM * 7 * 25 * 26]; // packed (Wm*C[j], exp(Wv)*sc2[j]*C[j]^2)
__device__ u64 g_W0[PPERM * 25];
__device__ float g_pm[PPERM * NSAMP];
__device__ float g_pv[PPERM * NSAMP];

__device__ __constant__ float BINC[25] = {
    1.f, 24.f, 276.f, 2024.f, 10626.f, 42504.f, 134596.f, 346104.f,
    735471.f, 1307504.f, 1961256.f, 2496144.f, 2704156.f, 2496144.f,
    1961256.f, 1307504.f, 735471.f, 346104.f, 134596.f, 42504.f,
    10626.f, 2024.f, 276.f, 24.f, 1.f};

// ---------------- f32x2 packed helpers (sm_100) ----------------
__device__ __forceinline__ u64 mul2(u64 a, u64 b) {
    u64 d; asm("mul.rn.f32x2 %0, %1, %2;" : "=l"(d) : "l"(a), "l"(b)); return d;
}
__device__ __forceinline__ void fma2(u64& d, u64 a, u64 b) {
    asm("fma.rn.f32x2 %0, %1, %2, %0;" : "+l"(d) : "l"(a), "l"(b));
}
__device__ __forceinline__ u64 add2r(u64 a, u64 b) {
    u64 d; asm("add.rn.f32x2 %0, %1, %2;" : "=l"(d) : "l"(a), "l"(b)); return d;
}
__device__ __forceinline__ u64 packf2(float lo, float hi) {
    u64 r; asm("mov.b64 %0, {%1, %2};" : "=l"(r) : "f"(lo), "f"(hi)); return r;
}
__device__ __forceinline__ void unpackf2(u64 v, float& lo, float& hi) {
    asm("mov.b64 {%0, %1}, %2;" : "=f"(lo), "=f"(hi) : "l"(v));
}
__device__ __forceinline__ void lds2(u64& a, u64& b, unsigned addr) {
    asm("ld.shared.v2.u64 {%0, %1}, [%2];" : "=l"(a), "=l"(b) : "r"(addr));
}

// ---------------- dummy (profiling slot alignment) ----------------
__global__ void k_dummy() {}

// ---------------- setup: sc2 = solve( (B(I)^2) x = 1 ) ----------------
__global__ void k_sc2() {
    __shared__ double A[25][26];
    __shared__ int piv;
    int t = threadIdx.x;
    if (t < 25) {
        float ti = (float)t / 24.0f;
        float om = 1.0f - ti;
        for (int k = 0; k < 25; k++) {
            float xk = (float)pow((double)ti, (double)k);
            float ym = (float)pow((double)om, (double)(24 - k));
            float val = (xk * ym) * BINC[k];
            A[t][k] = (double)(val * val);
        }
        A[t][25] = 1.0;
    }
    __syncthreads();
    for (int k = 0; k < 25; k++) {
        if (t == 0) {
            int pi = k; double best = fabs(A[k][k]);
            for (int i = k + 1; i < 25; i++) {
                double v = fabs(A[i][k]);
                if (v > best) { best = v; pi = i; }
            }
            piv = pi;
        }
        __syncthreads();
        int pv = piv;
        if (pv != k && t < 26) { double tmp = A[k][t]; A[k][t] = A[pv][t]; A[pv][t] = tmp; }
        __syncthreads();
        if (t < 25 && t != k) {
            double f = A[t][k] / A[k][k];
            for (int j = k; j < 26; j++) A[t][j] -= f * A[k][j];
        }
        __syncthreads();
    }
    if (t < 25) g_sc2[t] = (float)(A[t][25] / A[t][t]);
}

// ---------------- prep: interleaved, binomial-folded weights ----------------
__global__ void k_prep(const float* __restrict__ wmr, const float* __restrict__ wvr,
                       const float* __restrict__ wm0, const float* __restrict__ wv0) {
    const int NW = PPERM * 7 * 25 * 26;
    int i = blockIdx.x * blockDim.x + threadIdx.x;
    if (i < NW) {
        int p = i / 4550;  int r  = i - p * 4550;
        int l = r / 650;   int rr = r - l * 650;
        int k = rr / 26;   int j  = rr - k * 26;
        u64 v = 0;
        if (j < 25) {
            int src = ((l * 32 + p) * 25 + k) * 25 + j;
            float b  = BINC[j];
            float lo = wmr[src] * b;
            float hi = expf(wvr[src]) * g_sc2[j] * b * b;
            v = ((u64)__float_as_uint(hi) << 32) | (u64)__float_as_uint(lo);
        }
        g_W[i] = v;
    } else if (i < NW + PPERM * 25) {
        int r = i - NW; int p = r / 25; int j = r - p * 25;
        float b  = BINC[j];
        float lo = wm0[p * 25 + j] * b;
        float hi = expf(wv0[p * 25 + j]) * g_sc2[j] * b * b;
        g_W0[r] = ((u64)__float_as_uint(hi) << 32) | (u64)__float_as_uint(lo);
    }
}

// ---------------- main: one thread = one (sample, perm) ----------------
__global__ void __launch_bounds__(256, 2) k_main(
    const float* __restrict__ X, const int* __restrict__ perm,
    const float* __restrict__ pprec)
{
    __shared__ __align__(16) u64 sW[7 * 25 * 26];   // 36400 B
    __shared__ u64 s0[25];
    __shared__ int sperm[8];

    int p = blockIdx.y;
    int tid = threadIdx.x;

    {
        const float4* src4 = (const float4*)(g_W + p * 4550);
        float4* dst4 = (float4*)sW;
        #pragma unroll
        for (int i = 0; i < 2275; i += 256) {
            int e = i + tid;
            if (e < 2275) dst4[e] = src4[e];
        }
    }
    if (tid < 25) s0[tid] = g_W0[p * 25 + tid];
    if (tid < 8)  sperm[tid] = perm[p * 8 + tid];
    __syncthreads();

    int n = blockIdx.x * 256 + tid;
    const float* xr = X + n * 8;

    u64 f[25];   // packed (fm, fv)

    // level 0: f[j] = W0pre[j] * (u^j, u^2j) * (om^(24-j), om^(2(24-j)))
    {
        float u = __ldg(xr + sperm[0]);
        float om = 1.0f - u;
        u64 tm = packf2(u, u * u);
        u64 P = packf2(1.0f, 1.0f);
        #pragma unroll
        for (int j = 0; j < 25; j++) { f[j] = mul2(s0[j], P); P = mul2(P, tm); }
        u64 sm2 = packf2(om, om * om);
        u64 Q = packf2(1.0f, 1.0f);
        #pragma unroll
        for (int j = 24; j >= 0; j--) { f[j] = mul2(f[j], Q); Q = mul2(Q, sm2); }
    }

    unsigned wbase = (unsigned)__cvta_generic_to_shared(sW);

    #pragma unroll 1
    for (int l = 0; l < 7; l++) {
        unsigned rowa = wbase + (unsigned)(l * 650 * 8);
        u64 a[25];
        {   // k = 0 : init accumulators, streaming weights 16B at a time
            #pragma unroll
            for (int q = 0; q < 13; q++) {
                u64 w0, w1;
                lds2(w0, w1, rowa + q * 16);
                a[2 * q] = mul2(f[0], w0);
                if (q < 12) a[2 * q + 1] = mul2(f[0], w1);
            }
        }
        #pragma unroll
        for (int k = 1; k < 25; k++) {
            unsigned ra = rowa + (unsigned)(k * 208);
            #pragma unroll
            for (int q = 0; q < 13; q++) {
                u64 w0, w1;
                lds2(w0, w1, ra + q * 16);
                fma2(a[2 * q], f[k], w0);
                if (q < 12) fma2(a[2 * q + 1], f[k], w1);
            }
        }
        // epilogue: f[j] = a[j] * (u^j, u^2j) * (om^(24-j), om^(2(24-j)))
        float u = __ldg(xr + sperm[l + 1]);
        float om = 1.0f - u;
        u64 tm = packf2(u, u * u);
        u64 P = packf2(1.0f, 1.0f);
        #pragma unroll
        for (int j = 0; j < 25; j++) { a[j] = mul2(a[j], P); P = mul2(P, tm); }
        u64 sm2 = packf2(om, om * om);
        u64 Q = packf2(1.0f, 1.0f);
        #pragma unroll
        for (int j = 24; j >= 0; j--) { f[j] = mul2(a[j], Q); Q = mul2(Q, sm2); }
    }

    // tree reduction over j (packed); odd leftovers carry forward untouched
    #pragma unroll
    for (int j = 0; j < 12; j++) f[j] = add2r(f[j], f[j + 13]);  // 25 -> 13 (f[12] carries)
    #pragma unroll
    for (int j = 0; j < 6; j++)  f[j] = add2r(f[j], f[j + 7]);   // 13 -> 7 (f[6] carries)
    #pragma unroll
    for (int j = 0; j < 3; j++)  f[j] = add2r(f[j], f[j + 4]);   // 7 -> 4 (f[3] carries)
    f[0] = add2r(f[0], f[2]);
    f[1] = add2r(f[1], f[3]);
    f[0] = add2r(f[0], f[1]);
    float sm, sv; unpackf2(f[0], sm, sv);

    g_pm[p * NSAMP + n] = sm;
    g_pv[p * NSAMP + n] = sv / __ldg(pprec + p);
}

// ---------------- deterministic reduction over permutations ----------------
__global__ void k_reduce(float* __restrict__ out) {
    int n = blockIdx.x * blockDim.x + threadIdx.x;
    float sm = 0.f, sv = 0.f;
    #pragma unroll
    for (int p = 0; p < PPERM; p++) {
        sm += g_pm[p * NSAMP + n];
        sv += g_pv[p * NSAMP + n];
    }
    out[2 * n]     = sm;
    out[2 * n + 1] = sv;
}

extern "C" void kernel_launch(void* const* d_in, const int* in_sizes, int n_in,
                              void* d_out, int out_size) {
    const float* X    = (const float*)d_in[0];
    const int*   perm = (const int*)  d_in[1];
    const float* wm0  = (const float*)d_in[2];
    const float* wmr  = (const float*)d_in[3];
    const float* wv0  = (const float*)d_in[4];
    const float* wvr  = (const float*)d_in[5];
    const float* pp   = (const float*)d_in[6];

    const int NPREP = PPERM * 7 * 25 * 26 + PPERM * 25;
    k_dummy<<<1, 32>>>();   // pads launch index so ncu's skip-5 capture lands on k_main
    k_sc2<<<1, 32>>>();
    k_prep<<<(NPREP + 255) / 256, 256>>>(wmr, wvr, wm0, wv0);
    k_main<<<dim3(NSAMP / 256, PPERM), 256>>>(X, perm, pp);
    k_reduce<<<NSAMP / 256, 256>>>((float*)d_out);
}

// round 8
// speedup vs baseline: 1.2716x; 1.2716x over previous
#include <cuda_runtime.h>
#include <math.h>

// BernsteinNetwork: N=32768, D=8, ORDER=24, P=32
#define NSAMP 32768
#define PPERM 32

typedef unsigned long long u64;

// ---------------- scratch (no device allocation allowed) ----------------
__device__ float g_sc2[25];
__device__ __align__(16) u64 g_W [PPERM * 7 * 25 * 26]; // packed (Wm*C[j], exp(Wv)*sc2[j]*C[j]^2)
__device__ u64 g_W0[PPERM * 25];
__device__ float g_pm[PPERM * NSAMP];
__device__ float g_pv[PPERM * NSAMP];

__device__ __constant__ float BINC[25] = {
    1.f, 24.f, 276.f, 2024.f, 10626.f, 42504.f, 134596.f, 346104.f,
    735471.f, 1307504.f, 1961256.f, 2496144.f, 2704156.f, 2496144.f,
    1961256.f, 1307504.f, 735471.f, 346104.f, 134596.f, 42504.f,
    10626.f, 2024.f, 276.f, 24.f, 1.f};

// ---------------- f32x2 packed helpers (sm_100) ----------------
__device__ __forceinline__ u64 mul2(u64 a, u64 b) {
    u64 d; asm("mul.rn.f32x2 %0, %1, %2;" : "=l"(d) : "l"(a), "l"(b)); return d;
}
__device__ __forceinline__ void fma2(u64& d, u64 a, u64 b) {
    asm("fma.rn.f32x2 %0, %1, %2, %0;" : "+l"(d) : "l"(a), "l"(b));
}
__device__ __forceinline__ u64 add2r(u64 a, u64 b) {
    u64 d; asm("add.rn.f32x2 %0, %1, %2;" : "=l"(d) : "l"(a), "l"(b)); return d;
}
__device__ __forceinline__ u64 packf2(float lo, float hi) {
    u64 r; asm("mov.b64 %0, {%1, %2};" : "=l"(r) : "f"(lo), "f"(hi)); return r;
}
__device__ __forceinline__ void unpackf2(u64 v, float& lo, float& hi) {
    asm("mov.b64 {%0, %1}, %2;" : "=f"(lo), "=f"(hi) : "l"(v));
}
__device__ __forceinline__ void lds2(u64& a, u64& b, unsigned addr) {
    asm("ld.shared.v2.u64 {%0, %1}, [%2];" : "=l"(a), "=l"(b) : "r"(addr));
}

// ---------------- dummy (profiling slot alignment) ----------------
__global__ void k_dummy() {}

// ---------------- setup: sc2 = solve( (B(I)^2) x = 1 ) ----------------
__global__ void k_sc2() {
    __shared__ double A[25][26];
    __shared__ int piv;
    int t = threadIdx.x;
    if (t < 25) {
        float ti = (float)t / 24.0f;
        float om = 1.0f - ti;
        for (int k = 0; k < 25; k++) {
            float xk = (float)pow((double)ti, (double)k);
            float ym = (float)pow((double)om, (double)(24 - k));
            float val = (xk * ym) * BINC[k];
            A[t][k] = (double)(val * val);
        }
        A[t][25] = 1.0;
    }
    __syncthreads();
    for (int k = 0; k < 25; k++) {
        if (t == 0) {
            int pi = k; double best = fabs(A[k][k]);
            for (int i = k + 1; i < 25; i++) {
                double v = fabs(A[i][k]);
                if (v > best) { best = v; pi = i; }
            }
            piv = pi;
        }
        __syncthreads();
        int pv = piv;
        if (pv != k && t < 26) { double tmp = A[k][t]; A[k][t] = A[pv][t]; A[pv][t] = tmp; }
        __syncthreads();
        if (t < 25 && t != k) {
            double f = A[t][k] / A[k][k];
            for (int j = k; j < 26; j++) A[t][j] -= f * A[k][j];
        }
        __syncthreads();
    }
    if (t < 25) g_sc2[t] = (float)(A[t][25] / A[t][t]);
}

// ---------------- prep: interleaved, binomial-folded weights ----------------
__global__ void k_prep(const float* __restrict__ wmr, const float* __restrict__ wvr,
                       const float* __restrict__ wm0, const float* __restrict__ wv0) {
    const int NW = PPERM * 7 * 25 * 26;
    int i = blockIdx.x * blockDim.x + threadIdx.x;
    if (i < NW) {
        int p = i / 4550;  int r  = i - p * 4550;
        int l = r / 650;   int rr = r - l * 650;
        int k = rr / 26;   int j  = rr - k * 26;
        u64 v = 0;
        if (j < 25) {
            int src = ((l * 32 + p) * 25 + k) * 25 + j;
            float b  = BINC[j];
            float lo = wmr[src] * b;
            float hi = expf(wvr[src]) * g_sc2[j] * b * b;
            v = ((u64)__float_as_uint(hi) << 32) | (u64)__float_as_uint(lo);
        }
        g_W[i] = v;
    } else if (i < NW + PPERM * 25) {
        int r = i - NW; int p = r / 25; int j = r - p * 25;
        float b  = BINC[j];
        float lo = wm0[p * 25 + j] * b;
        float hi = expf(wv0[p * 25 + j]) * g_sc2[j] * b * b;
        g_W0[r] = ((u64)__float_as_uint(hi) << 32) | (u64)__float_as_uint(lo);
    }
}

// ---------------- main: one thread = TWO (sample, perm) pairs ----------------
// Each weight LDS now feeds 4 fma2 (2 samples x 2 cols), halving L1 wavefronts
// per sample. ~225 regs -> 1 CTA/SM; latency hidden by ILP (50 indep fma2/k).
__global__ void __launch_bounds__(256, 1) k_main(
    const float* __restrict__ X, const int* __restrict__ perm,
    const float* __restrict__ pprec)
{
    __shared__ __align__(16) u64 sW[7 * 25 * 26];   // 36400 B
    __shared__ u64 s0[25];
    __shared__ int sperm[8];

    int p = blockIdx.y;
    int tid = threadIdx.x;

    {
        const float4* src4 = (const float4*)(g_W + p * 4550);
        float4* dst4 = (float4*)sW;
        #pragma unroll
        for (int i = 0; i < 2275; i += 256) {
            int e = i + tid;
            if (e < 2275) dst4[e] = src4[e];
        }
    }
    if (tid < 25) s0[tid] = g_W0[p * 25 + tid];
    if (tid < 8)  sperm[tid] = perm[p * 8 + tid];
    __syncthreads();

    int n0 = blockIdx.x * 512 + tid;
    int n1 = n0 + 256;
    const float* xr0 = X + n0 * 8;
    const float* xr1 = X + n1 * 8;

    u64 f0[25], f1[25];   // packed (fm, fv) per sample

    // level 0
    {
        float ua = __ldg(xr0 + sperm[0]);
        float ub = __ldg(xr1 + sperm[0]);
        float oa = 1.0f - ua, ob = 1.0f - ub;
        u64 ta = packf2(ua, ua * ua), tb = packf2(ub, ub * ub);
        u64 Pa = packf2(1.0f, 1.0f), Pb = Pa;
        #pragma unroll
        for (int j = 0; j < 25; j++) {
            f0[j] = mul2(s0[j], Pa); Pa = mul2(Pa, ta);
            f1[j] = mul2(s0[j], Pb); Pb = mul2(Pb, tb);
        }
        u64 sa = packf2(oa, oa * oa), sb = packf2(ob, ob * ob);
        u64 Qa = packf2(1.0f, 1.0f), Qb = Qa;
        #pragma unroll
        for (int j = 24; j >= 0; j--) {
            f0[j] = mul2(f0[j], Qa); Qa = mul2(Qa, sa);
            f1[j] = mul2(f1[j], Qb); Qb = mul2(Qb, sb);
        }
    }

    unsigned wbase = (unsigned)__cvta_generic_to_shared(sW);

    #pragma unroll 1
    for (int l = 0; l < 7; l++) {
        unsigned rowa = wbase + (unsigned)(l * 650 * 8);
        u64 a0[25], a1[25];
        {   // k = 0 : init accumulators
            #pragma unroll
            for (int q = 0; q < 13; q++) {
                u64 w0, w1;
                lds2(w0, w1, rowa + q * 16);
                a0[2 * q] = mul2(f0[0], w0);
                a1[2 * q] = mul2(f1[0], w0);
                if (q < 12) { a0[2 * q + 1] = mul2(f0[0], w1); a1[2 * q + 1] = mul2(f1[0], w1); }
            }
        }
        #pragma unroll
        for (int k = 1; k < 25; k++) {
            unsigned ra = rowa + (unsigned)(k * 208);
            #pragma unroll
            for (int q = 0; q < 13; q++) {
                u64 w0, w1;
                lds2(w0, w1, ra + q * 16);
                fma2(a0[2 * q], f0[k], w0);
                fma2(a1[2 * q], f1[k], w0);
                if (q < 12) { fma2(a0[2 * q + 1], f0[k], w1); fma2(a1[2 * q + 1], f1[k], w1); }
            }
        }
        // epilogue: f[j] = a[j] * (u^j, u^2j) * (om^(24-j), om^(2(24-j)))
        float ua = __ldg(xr0 + sperm[l + 1]);
        float ub = __ldg(xr1 + sperm[l + 1]);
        float oa = 1.0f - ua, ob = 1.0f - ub;
        u64 ta = packf2(ua, ua * ua), tb = packf2(ub, ub * ub);
        u64 Pa = packf2(1.0f, 1.0f), Pb = Pa;
        #pragma unroll
        for (int j = 0; j < 25; j++) {
            a0[j] = mul2(a0[j], Pa); Pa = mul2(Pa, ta);
            a1[j] = mul2(a1[j], Pb); Pb = mul2(Pb, tb);
        }
        u64 sa = packf2(oa, oa * oa), sb = packf2(ob, ob * ob);
        u64 Qa = packf2(1.0f, 1.0f), Qb = Qa;
        #pragma unroll
        for (int j = 24; j >= 0; j--) {
            f0[j] = mul2(a0[j], Qa); Qa = mul2(Qa, sa);
            f1[j] = mul2(a1[j], Qb); Qb = mul2(Qb, sb);
        }
    }

    // tree reduction over j (packed); odd leftovers carry forward
    #pragma unroll
    for (int j = 0; j < 12; j++) { f0[j] = add2r(f0[j], f0[j + 13]); f1[j] = add2r(f1[j], f1[j + 13]); }
    #pragma unroll
    for (int j = 0; j < 6; j++)  { f0[j] = add2r(f0[j], f0[j + 7]);  f1[j] = add2r(f1[j], f1[j + 7]); }
    #pragma unroll
    for (int j = 0; j < 3; j++)  { f0[j] = add2r(f0[j], f0[j + 4]);  f1[j] = add2r(f1[j], f1[j + 4]); }
    f0[0] = add2r(f0[0], f0[2]); f0[1] = add2r(f0[1], f0[3]); f0[0] = add2r(f0[0], f0[1]);
    f1[0] = add2r(f1[0], f1[2]); f1[1] = add2r(f1[1], f1[3]); f1[0] = add2r(f1[0], f1[1]);

    float invp = 1.0f / __ldg(pprec + p);
    float sm0, sv0, sm1, sv1;
    unpackf2(f0[0], sm0, sv0);
    unpackf2(f1[0], sm1, sv1);
    g_pm[p * NSAMP + n0] = sm0;
    g_pv[p * NSAMP + n0] = sv0 * invp;
    g_pm[p * NSAMP + n1] = sm1;
    g_pv[p * NSAMP + n1] = sv1 * invp;
}

// ---------------- deterministic reduction over permutations ----------------
__global__ void k_reduce(float* __restrict__ out) {
    int n = blockIdx.x * blockDim.x + threadIdx.x;
    float sm = 0.f, sv = 0.f;
    #pragma unroll
    for (int p = 0; p < PPERM; p++) {
        sm += g_pm[p * NSAMP + n];
        sv += g_pv[p * NSAMP + n];
    }
    out[2 * n]     = sm;
    out[2 * n + 1] = sv;
}

extern "C" void kernel_launch(void* const* d_in, const int* in_sizes, int n_in,
                              void* d_out, int out_size) {
    const float* X    = (const float*)d_in[0];
    const int*   perm = (const int*)  d_in[1];
    const float* wm0  = (const float*)d_in[2];
    const float* wmr  = (const float*)d_in[3];
    const float* wv0  = (const float*)d_in[4];
    const float* wvr  = (const float*)d_in[5];
    const float* pp   = (const float*)d_in[6];

    const int NPREP = PPERM * 7 * 25 * 26 + PPERM * 25;
    k_dummy<<<1, 32>>>();   // pads launch index so ncu's skip-5 capture lands on k_main
    k_sc2<<<1, 32>>>();
    k_prep<<<(NPREP + 255) / 256, 256>>>(wmr, wvr, wm0, wv0);
    k_main<<<dim3(NSAMP / 512, PPERM), 256>>>(X, perm, pp);
    k_reduce<<<NSAMP / 256, 256>>>((float*)d_out);
}

// round 9
// speedup vs baseline: 1.2938x; 1.0174x over previous
#include <cuda_runtime.h>
#include <math.h>

// BernsteinNetwork: N=32768, D=8, ORDER=24, P=32
#define NSAMP 32768
#define PPERM 32

typedef unsigned long long u64;

// ---------------- scratch (no device allocation allowed) ----------------
__device__ float g_sc2[25];
__device__ __align__(16) u64 g_W [PPERM * 7 * 25 * 26]; // packed (Wm*C[j], exp(Wv)*sc2[j]*C[j]^2)
__device__ u64 g_W0[PPERM * 25];
__device__ float g_pm[PPERM * NSAMP];
__device__ float g_pv[PPERM * NSAMP];

__device__ __constant__ float BINC[25] = {
    1.f, 24.f, 276.f, 2024.f, 10626.f, 42504.f, 134596.f, 346104.f,
    735471.f, 1307504.f, 1961256.f, 2496144.f, 2704156.f, 2496144.f,
    1961256.f, 1307504.f, 735471.f, 346104.f, 134596.f, 42504.f,
    10626.f, 2024.f, 276.f, 24.f, 1.f};

// ---------------- f32x2 packed helpers (sm_100) ----------------
__device__ __forceinline__ u64 mul2(u64 a, u64 b) {
    u64 d; asm("mul.rn.f32x2 %0, %1, %2;" : "=l"(d) : "l"(a), "l"(b)); return d;
}
__device__ __forceinline__ void fma2(u64& d, u64 a, u64 b) {
    asm("fma.rn.f32x2 %0, %1, %2, %0;" : "+l"(d) : "l"(a), "l"(b));
}
__device__ __forceinline__ u64 add2r(u64 a, u64 b) {
    u64 d; asm("add.rn.f32x2 %0, %1, %2;" : "=l"(d) : "l"(a), "l"(b)); return d;
}
__device__ __forceinline__ u64 packf2(float lo, float hi) {
    u64 r; asm("mov.b64 %0, {%1, %2};" : "=l"(r) : "f"(lo), "f"(hi)); return r;
}
__device__ __forceinline__ void unpackf2(u64 v, float& lo, float& hi) {
    asm("mov.b64 {%0, %1}, %2;" : "=f"(lo), "=f"(hi) : "l"(v));
}
__device__ __forceinline__ void lds2(u64& a, u64& b, unsigned addr) {
    asm("ld.shared.v2.u64 {%0, %1}, [%2];" : "=l"(a), "=l"(b) : "r"(addr));
}

// ---------------- dummy (profiling slot alignment) ----------------
__global__ void k_dummy() {}

// ---------------- setup: sc2 = solve( (B(I)^2) x = 1 ) ----------------
__global__ void k_sc2() {
    __shared__ double A[25][26];
    __shared__ int piv;
    int t = threadIdx.x;
    if (t < 25) {
        float ti = (float)t / 24.0f;
        float om = 1.0f - ti;
        for (int k = 0; k < 25; k++) {
            float xk = (float)pow((double)ti, (double)k);
            float ym = (float)pow((double)om, (double)(24 - k));
            float val = (xk * ym) * BINC[k];
            A[t][k] = (double)(val * val);
        }
        A[t][25] = 1.0;
    }
    __syncthreads();
    for (int k = 0; k < 25; k++) {
        if (t == 0) {
            int pi = k; double best = fabs(A[k][k]);
            for (int i = k + 1; i < 25; i++) {
                double v = fabs(A[i][k]);
                if (v > best) { best = v; pi = i; }
            }
            piv = pi;
        }
        __syncthreads();
        int pv = piv;
        if (pv != k && t < 26) { double tmp = A[k][t]; A[k][t] = A[pv][t]; A[pv][t] = tmp; }
        __syncthreads();
        if (t < 25 && t != k) {
            double f = A[t][k] / A[k][k];
            for (int j = k; j < 26; j++) A[t][j] -= f * A[k][j];
        }
        __syncthreads();
    }
    if (t < 25) g_sc2[t] = (float)(A[t][25] / A[t][t]);
}

// ---------------- prep: interleaved, binomial-folded weights ----------------
__global__ void k_prep(const float* __restrict__ wmr, const float* __restrict__ wvr,
                       const float* __restrict__ wm0, const float* __restrict__ wv0) {
    const int NW = PPERM * 7 * 25 * 26;
    int i = blockIdx.x * blockDim.x + threadIdx.x;
    if (i < NW) {
        int p = i / 4550;  int r  = i - p * 4550;
        int l = r / 650;   int rr = r - l * 650;
        int k = rr / 26;   int j  = rr - k * 26;
        u64 v = 0;
        if (j < 25) {
            int src = ((l * 32 + p) * 25 + k) * 25 + j;
            float b  = BINC[j];
            float lo = wmr[src] * b;
            float hi = expf(wvr[src]) * g_sc2[j] * b * b;
            v = ((u64)__float_as_uint(hi) << 32) | (u64)__float_as_uint(lo);
        }
        g_W[i] = v;
    } else if (i < NW + PPERM * 25) {
        int r = i - NW; int p = r / 25; int j = r - p * 25;
        float b  = BINC[j];
        float lo = wm0[p * 25 + j] * b;
        float hi = expf(wv0[p * 25 + j]) * g_sc2[j] * b * b;
        g_W0[r] = ((u64)__float_as_uint(hi) << 32) | (u64)__float_as_uint(lo);
    }
}

// ---------------- main: one thread = TWO (sample, perm) pairs ----------------
// 128-thread CTAs, 2 CTAs/SM: the two warps sharing each SMSP come from
// independent CTAs at staggered progress, so LDS bursts / epilogue chains
// anti-phase instead of stalling in lockstep.
__global__ void __launch_bounds__(128, 2) k_main(
    const float* __restrict__ X, const int* __restrict__ perm,
    const float* __restrict__ pprec)
{
    __shared__ __align__(16) u64 sW[7 * 25 * 26];   // 36400 B
    __shared__ u64 s0[25];
    __shared__ int sperm[8];

    int p = blockIdx.y;
    int tid = threadIdx.x;

    {
        const float4* src4 = (const float4*)(g_W + p * 4550);
        float4* dst4 = (float4*)sW;
        for (int e = tid; e < 2275; e += 128) dst4[e] = src4[e];
    }
    if (tid < 25) s0[tid] = g_W0[p * 25 + tid];
    if (tid < 8)  sperm[tid] = perm[p * 8 + tid];
    __syncthreads();

    int n0 = blockIdx.x * 256 + tid;
    int n1 = n0 + 128;
    const float* xr0 = X + n0 * 8;
    const float* xr1 = X + n1 * 8;

    u64 f0[25], f1[25];   // packed (fm, fv) per sample

    // level 0
    {
        float ua = __ldg(xr0 + sperm[0]);
        float ub = __ldg(xr1 + sperm[0]);
        float oa = 1.0f - ua, ob = 1.0f - ub;
        u64 ta = packf2(ua, ua * ua), tb = packf2(ub, ub * ub);
        u64 Pa = packf2(1.0f, 1.0f), Pb = Pa;
        #pragma unroll
        for (int j = 0; j < 25; j++) {
            f0[j] = mul2(s0[j], Pa); Pa = mul2(Pa, ta);
            f1[j] = mul2(s0[j], Pb); Pb = mul2(Pb, tb);
        }
        u64 sa = packf2(oa, oa * oa), sb = packf2(ob, ob * ob);
        u64 Qa = packf2(1.0f, 1.0f), Qb = Qa;
        #pragma unroll
        for (int j = 24; j >= 0; j--) {
            f0[j] = mul2(f0[j], Qa); Qa = mul2(Qa, sa);
            f1[j] = mul2(f1[j], Qb); Qb = mul2(Qb, sb);
        }
    }

    unsigned wbase = (unsigned)__cvta_generic_to_shared(sW);

    #pragma unroll 1
    for (int l = 0; l < 7; l++) {
        unsigned rowa = wbase + (unsigned)(l * 650 * 8);
        u64 a0[25], a1[25];
        {   // k = 0 : init accumulators
            #pragma unroll
            for (int q = 0; q < 13; q++) {
                u64 w0, w1;
                lds2(w0, w1, rowa + q * 16);
                a0[2 * q] = mul2(f0[0], w0);
                a1[2 * q] = mul2(f1[0], w0);
                if (q < 12) { a0[2 * q + 1] = mul2(f0[0], w1); a1[2 * q + 1] = mul2(f1[0], w1); }
            }
        }
        #pragma unroll
        for (int k = 1; k < 25; k++) {
            unsigned ra = rowa + (unsigned)(k * 208);
            #pragma unroll
            for (int q = 0; q < 13; q++) {
                u64 w0, w1;
                lds2(w0, w1, ra + q * 16);
                fma2(a0[2 * q], f0[k], w0);
                fma2(a1[2 * q], f1[k], w0);
                if (q < 12) { fma2(a0[2 * q + 1], f0[k], w1); fma2(a1[2 * q + 1], f1[k], w1); }
            }
        }
        // epilogue: f[j] = a[j] * (u^j, u^2j) * (om^(24-j), om^(2(24-j)))
        float ua = __ldg(xr0 + sperm[l + 1]);
        float ub = __ldg(xr1 + sperm[l + 1]);
        float oa = 1.0f - ua, ob = 1.0f - ub;
        u64 ta = packf2(ua, ua * ua), tb = packf2(ub, ub * ub);
        u64 Pa = packf2(1.0f, 1.0f), Pb = Pa;
        #pragma unroll
        for (int j = 0; j < 25; j++) {
            a0[j] = mul2(a0[j], Pa); Pa = mul2(Pa, ta);
            a1[j] = mul2(a1[j], Pb); Pb = mul2(Pb, tb);
        }
        u64 sa = packf2(oa, oa * oa), sb = packf2(ob, ob * ob);
        u64 Qa = packf2(1.0f, 1.0f), Qb = Qa;
        #pragma unroll
        for (int j = 24; j >= 0; j--) {
            f0[j] = mul2(a0[j], Qa); Qa = mul2(Qa, sa);
            f1[j] = mul2(a1[j], Qb); Qb = mul2(Qb, sb);
        }
    }

    // tree reduction over j (packed); odd leftovers carry forward
    #pragma unroll
    for (int j = 0; j < 12; j++) { f0[j] = add2r(f0[j], f0[j + 13]); f1[j] = add2r(f1[j], f1[j + 13]); }
    #pragma unroll
    for (int j = 0; j < 6; j++)  { f0[j] = add2r(f0[j], f0[j + 7]);  f1[j] = add2r(f1[j], f1[j + 7]); }
    #pragma unroll
    for (int j = 0; j < 3; j++)  { f0[j] = add2r(f0[j], f0[j + 4]);  f1[j] = add2r(f1[j], f1[j + 4]); }
    f0[0] = add2r(f0[0], f0[2]); f0[1] = add2r(f0[1], f0[3]); f0[0] = add2r(f0[0], f0[1]);
    f1[0] = add2r(f1[0], f1[2]); f1[1] = add2r(f1[1], f1[3]); f1[0] = add2r(f1[0], f1[1]);

    float invp = 1.0f / __ldg(pprec + p);
    float sm0, sv0, sm1, sv1;
    unpackf2(f0[0], sm0, sv0);
    unpackf2(f1[0], sm1, sv1);
    g_pm[p * NSAMP + n0] = sm0;
    g_pv[p * NSAMP + n0] = sv0 * invp;
    g_pm[p * NSAMP + n1] = sm1;
    g_pv[p * NSAMP + n1] = sv1 * invp;
}

// ---------------- deterministic reduction over permutations ----------------
__global__ void k_reduce(float* __restrict__ out) {
    int n = blockIdx.x * blockDim.x + threadIdx.x;
    float sm = 0.f, sv = 0.f;
    #pragma unroll
    for (int p = 0; p < PPERM; p++) {
        sm += g_pm[p * NSAMP + n];
        sv += g_pv[p * NSAMP + n];
    }
    out[2 * n]     = sm;
    out[2 * n + 1] = sv;
}

extern "C" void kernel_launch(void* const* d_in, const int* in_sizes, int n_in,
                              void* d_out, int out_size) {
    const float* X    = (const float*)d_in[0];
    const int*   perm = (const int*)  d_in[1];
    const float* wm0  = (const float*)d_in[2];
    const float* wmr  = (const float*)d_in[3];
    const float* wv0  = (const float*)d_in[4];
    const float* wvr  = (const float*)d_in[5];
    const float* pp   = (const float*)d_in[6];

    const int NPREP = PPERM * 7 * 25 * 26 + PPERM * 25;
    k_dummy<<<1, 32>>>();   // pads launch index so ncu's skip-5 capture lands on k_main
    k_sc2<<<1, 32>>>();
    k_prep<<<(NPREP + 255) / 256, 256>>>(wmr, wvr, wm0, wv0);
    k_main<<<dim3(NSAMP / 256, PPERM), 128>>>(X, perm, pp);
    k_reduce<<<NSAMP / 256, 256>>>((float*)d_out);
}

// round 10
// speedup vs baseline: 1.2970x; 1.0025x over previous
#include <cuda_runtime.h>
#include <math.h>

// BernsteinNetwork: N=32768, D=8, ORDER=24, P=32
#define NSAMP 32768
#define PPERM 32

typedef unsigned long long u64;

// ---------------- scratch (no device allocation allowed) ----------------
__device__ float g_sc2[25];
__device__ __align__(16) u64 g_W [PPERM * 7 * 25 * 26]; // packed (Wm*C[j], exp(Wv)*sc2[j]*C[j]^2)
__device__ u64 g_W0[PPERM * 25];
__device__ float g_pm[PPERM * NSAMP];
__device__ float g_pv[PPERM * NSAMP];

__device__ __constant__ float BINC[25] = {
    1.f, 24.f, 276.f, 2024.f, 10626.f, 42504.f, 134596.f, 346104.f,
    735471.f, 1307504.f, 1961256.f, 2496144.f, 2704156.f, 2496144.f,
    1961256.f, 1307504.f, 735471.f, 346104.f, 134596.f, 42504.f,
    10626.f, 2024.f, 276.f, 24.f, 1.f};

// ---------------- f32x2 packed helpers (sm_100) ----------------
__device__ __forceinline__ u64 mul2(u64 a, u64 b) {
    u64 d; asm("mul.rn.f32x2 %0, %1, %2;" : "=l"(d) : "l"(a), "l"(b)); return d;
}
__device__ __forceinline__ void fma2(u64& d, u64 a, u64 b) {
    asm("fma.rn.f32x2 %0, %1, %2, %0;" : "+l"(d) : "l"(a), "l"(b));
}
__device__ __forceinline__ u64 add2r(u64 a, u64 b) {
    u64 d; asm("add.rn.f32x2 %0, %1, %2;" : "=l"(d) : "l"(a), "l"(b)); return d;
}
__device__ __forceinline__ u64 packf2(float lo, float hi) {
    u64 r; asm("mov.b64 %0, {%1, %2};" : "=l"(r) : "f"(lo), "f"(hi)); return r;
}
__device__ __forceinline__ void unpackf2(u64 v, float& lo, float& hi) {
    asm("mov.b64 {%0, %1}, %2;" : "=f"(lo), "=f"(hi) : "l"(v));
}
__device__ __forceinline__ void lds2(u64& a, u64& b, unsigned addr) {
    asm("ld.shared.v2.u64 {%0, %1}, [%2];" : "=l"(a), "=l"(b) : "r"(addr));
}

// ---------------- dummy (profiling slot alignment) ----------------
__global__ void k_dummy() {}

// ---------------- setup: sc2 = solve( (B(I)^2) x = 1 ) ----------------
__global__ void k_sc2() {
    __shared__ double A[25][26];
    __shared__ int piv;
    int t = threadIdx.x;
    if (t < 25) {
        float ti = (float)t / 24.0f;
        float om = 1.0f - ti;
        for (int k = 0; k < 25; k++) {
            float xk = (float)pow((double)ti, (double)k);
            float ym = (float)pow((double)om, (double)(24 - k));
            float val = (xk * ym) * BINC[k];
            A[t][k] = (double)(val * val);
        }
        A[t][25] = 1.0;
    }
    __syncthreads();
    for (int k = 0; k < 25; k++) {
        if (t == 0) {
            int pi = k; double best = fabs(A[k][k]);
            for (int i = k + 1; i < 25; i++) {
                double v = fabs(A[i][k]);
                if (v > best) { best = v; pi = i; }
            }
            piv = pi;
        }
        __syncthreads();
        int pv = piv;
        if (pv != k && t < 26) { double tmp = A[k][t]; A[k][t] = A[pv][t]; A[pv][t] = tmp; }
        __syncthreads();
        if (t < 25 && t != k) {
            double f = A[t][k] / A[k][k];
            for (int j = k; j < 26; j++) A[t][j] -= f * A[k][j];
        }
        __syncthreads();
    }
    if (t < 25) g_sc2[t] = (float)(A[t][25] / A[t][t]);
}

// ---------------- prep: interleaved, binomial-folded weights ----------------
__global__ void k_prep(const float* __restrict__ wmr, const float* __restrict__ wvr,
                       const float* __restrict__ wm0, const float* __restrict__ wv0) {
    const int NW = PPERM * 7 * 25 * 26;
    int i = blockIdx.x * blockDim.x + threadIdx.x;
    if (i < NW) {
        int p = i / 4550;  int r  = i - p * 4550;
        int l = r / 650;   int rr = r - l * 650;
        int k = rr / 26;   int j  = rr - k * 26;
        u64 v = 0;
        if (j < 25) {
            int src = ((l * 32 + p) * 25 + k) * 25 + j;
            float b  = BINC[j];
            float lo = wmr[src] * b;
            float hi = expf(wvr[src]) * g_sc2[j] * b * b;
            v = ((u64)__float_as_uint(hi) << 32) | (u64)__float_as_uint(lo);
        }
        g_W[i] = v;
    } else if (i < NW + PPERM * 25) {
        int r = i - NW; int p = r / 25; int j = r - p * 25;
        float b  = BINC[j];
        float lo = wm0[p * 25 + j] * b;
        float hi = expf(wv0[p * 25 + j]) * g_sc2[j] * b * b;
        g_W0[r] = ((u64)__float_as_uint(hi) << 32) | (u64)__float_as_uint(lo);
    }
}

// ---------------- main: one thread = TWO (sample, perm) pairs ----------------
// 128-thread CTAs, 2 CTAs/SM: the two warps sharing each SMSP come from
// independent CTAs at staggered progress, so LDS bursts / epilogue chains
// anti-phase instead of stalling in lockstep.
__global__ void __launch_bounds__(128, 2) k_main(
    const float* __restrict__ X, const int* __restrict__ perm,
    const float* __restrict__ pprec)
{
    __shared__ __align__(16) u64 sW[7 * 25 * 26];   // 36400 B
    __shared__ u64 s0[25];
    __shared__ int sperm[8];

    int p = blockIdx.y;
    int tid = threadIdx.x;

    {
        const float4* src4 = (const float4*)(g_W + p * 4550);
        float4* dst4 = (float4*)sW;
        for (int e = tid; e < 2275; e += 128) dst4[e] = src4[e];
    }
    if (tid < 25) s0[tid] = g_W0[p * 25 + tid];
    if (tid < 8)  sperm[tid] = perm[p * 8 + tid];
    __syncthreads();

    int n0 = blockIdx.x * 256 + tid;
    int n1 = n0 + 128;
    const float* xr0 = X + n0 * 8;
    const float* xr1 = X + n1 * 8;

    u64 f0[25], f1[25];   // packed (fm, fv) per sample

    // level 0
    {
        float ua = __ldg(xr0 + sperm[0]);
        float ub = __ldg(xr1 + sperm[0]);
        float oa = 1.0f - ua, ob = 1.0f - ub;
        u64 ta = packf2(ua, ua * ua), tb = packf2(ub, ub * ub);
        u64 Pa = packf2(1.0f, 1.0f), Pb = Pa;
        #pragma unroll
        for (int j = 0; j < 25; j++) {
            f0[j] = mul2(s0[j], Pa); Pa = mul2(Pa, ta);
            f1[j] = mul2(s0[j], Pb); Pb = mul2(Pb, tb);
        }
        u64 sa = packf2(oa, oa * oa), sb = packf2(ob, ob * ob);
        u64 Qa = packf2(1.0f, 1.0f), Qb = Qa;
        #pragma unroll
        for (int j = 24; j >= 0; j--) {
            f0[j] = mul2(f0[j], Qa); Qa = mul2(Qa, sa);
            f1[j] = mul2(f1[j], Qb); Qb = mul2(Qb, sb);
        }
    }

    unsigned wbase = (unsigned)__cvta_generic_to_shared(sW);

    #pragma unroll 1
    for (int l = 0; l < 7; l++) {
        unsigned rowa = wbase + (unsigned)(l * 650 * 8);
        u64 a0[25], a1[25];
        {   // k = 0 : init accumulators
            #pragma unroll
            for (int q = 0; q < 13; q++) {
                u64 w0, w1;
                lds2(w0, w1, rowa + q * 16);
                a0[2 * q] = mul2(f0[0], w0);
                a1[2 * q] = mul2(f1[0], w0);
                if (q < 12) { a0[2 * q + 1] = mul2(f0[0], w1); a1[2 * q + 1] = mul2(f1[0], w1); }
            }
        }
        #pragma unroll
        for (int k = 1; k < 25; k++) {
            unsigned ra = rowa + (unsigned)(k * 208);
            #pragma unroll
            for (int q = 0; q < 13; q++) {
                u64 w0, w1;
                lds2(w0, w1, ra + q * 16);
                fma2(a0[2 * q], f0[k], w0);
                fma2(a1[2 * q], f1[k], w0);
                if (q < 12) { fma2(a0[2 * q + 1], f0[k], w1); fma2(a1[2 * q + 1], f1[k], w1); }
            }
        }
        // epilogue: f[j] = a[j] * (u^j, u^2j) * (om^(24-j), om^(2(24-j)))
        float ua = __ldg(xr0 + sperm[l + 1]);
        float ub = __ldg(xr1 + sperm[l + 1]);
        float oa = 1.0f - ua, ob = 1.0f - ub;
        u64 ta = packf2(ua, ua * ua), tb = packf2(ub, ub * ub);
        u64 Pa = packf2(1.0f, 1.0f), Pb = Pa;
        #pragma unroll
        for (int j = 0; j < 25; j++) {
            a0[j] = mul2(a0[j], Pa); Pa = mul2(Pa, ta);
            a1[j] = mul2(a1[j], Pb); Pb = mul2(Pb, tb);
        }
        u64 sa = packf2(oa, oa * oa), sb = packf2(ob, ob * ob);
        u64 Qa = packf2(1.0f, 1.0f), Qb = Qa;
        #pragma unroll
        for (int j = 24; j >= 0; j--) {
            f0[j] = mul2(a0[j], Qa); Qa = mul2(Qa, sa);
            f1[j] = mul2(a1[j], Qb); Qb = mul2(Qb, sb);
        }
    }

    // tree reduction over j (packed); odd leftovers carry forward
    #pragma unroll
    for (int j = 0; j < 12; j++) { f0[j] = add2r(f0[j], f0[j + 13]); f1[j] = add2r(f1[j], f1[j + 13]); }
    #pragma unroll
    for (int j = 0; j < 6; j++)  { f0[j] = add2r(f0[j], f0[j + 7]);  f1[j] = add2r(f1[j], f1[j + 7]); }
    #pragma unroll
    for (int j = 0; j < 3; j++)  { f0[j] = add2r(f0[j], f0[j + 4]);  f1[j] = add2r(f1[j], f1[j + 4]); }
    f0[0] = add2r(f0[0], f0[2]); f0[1] = add2r(f0[1], f0[3]); f0[0] = add2r(f0[0], f0[1]);
    f1[0] = add2r(f1[0], f1[2]); f1[1] = add2r(f1[1], f1[3]); f1[0] = add2r(f1[0], f1[1]);

    float invp = 1.0f / __ldg(pprec + p);
    float sm0, sv0, sm1, sv1;
    unpackf2(f0[0], sm0, sv0);
    unpackf2(f1[0], sm1, sv1);
    g_pm[p * NSAMP + n0] = sm0;
    g_pv[p * NSAMP + n0] = sv0 * invp;
    g_pm[p * NSAMP + n1] = sm1;
    g_pv[p * NSAMP + n1] = sv1 * invp;
}

// ---------------- deterministic reduction over permutations ----------------
__global__ void k_reduce(float* __restrict__ out) {
    int n = blockIdx.x * blockDim.x + threadIdx.x;
    float sm = 0.f, sv = 0.f;
    #pragma unroll
    for (int p = 0; p < PPERM; p++) {
        sm += g_pm[p * NSAMP + n];
        sv += g_pv[p * NSAMP + n];
    }
    out[2 * n]     = sm;
    out[2 * n + 1] = sv;
}

extern "C" void kernel_launch(void* const* d_in, const int* in_sizes, int n_in,
                              void* d_out, int out_size) {
    const float* X    = (const float*)d_in[0];
    const int*   perm = (const int*)  d_in[1];
    const float* wm0  = (const float*)d_in[2];
    const float* wmr  = (const float*)d_in[3];
    const float* wv0  = (const float*)d_in[4];
    const float* wvr  = (const float*)d_in[5];
    const float* pp   = (const float*)d_in[6];

    const int NPREP = PPERM * 7 * 25 * 26 + PPERM * 25;
    k_dummy<<<1, 32>>>();   // pads launch index so ncu's skip-5 capture lands on k_main
    k_sc2<<<1, 32>>>();
    k_prep<<<(NPREP + 255) / 256, 256>>>(wmr, wvr, wm0, wv0);
    k_main<<<dim3(NSAMP / 256, PPERM), 128>>>(X, perm, pp);
    k_reduce<<<NSAMP / 256, 256>>>((float*)d_out);
}

// round 11
// speedup vs baseline: 1.6858x; 1.2997x over previous
#include <cuda_runtime.h>
#include <cuda_bf16.h>
#include <math.h>

#define NSAMP 32768
#define PPERM 32
typedef unsigned long long u64;
typedef unsigned int u32;

// ---------------- scratch ----------------
__device__ float g_sc2[25];
__device__ u64 g_W0[PPERM * 25];
__device__ __align__(16) unsigned short g_Wf[PPERM * 28672]; // B-fragment table 57344 B/perm
__device__ float g_pm[PPERM * NSAMP];
__device__ float g_pv[PPERM * NSAMP];

__device__ __constant__ float BINC[25] = {
    1.f, 24.f, 276.f, 2024.f, 10626.f, 42504.f, 134596.f, 346104.f,
    735471.f, 1307504.f, 1961256.f, 2496144.f, 2704156.f, 2496144.f,
    1961256.f, 1307504.f, 735471.f, 346104.f, 134596.f, 42504.f,
    10626.f, 2024.f, 276.f, 24.f, 1.f};

// ---------------- helpers ----------------
__device__ __forceinline__ void mma16816(float d[4], const u32 a[4], u32 b0, u32 b1) {
    asm volatile("mma.sync.aligned.m16n8k16.row.col.f32.bf16.bf16.f32 "
        "{%0,%1,%2,%3}, {%4,%5,%6,%7}, {%8,%9}, {%0,%1,%2,%3};"
        : "+f"(d[0]), "+f"(d[1]), "+f"(d[2]), "+f"(d[3])
        : "r"(a[0]), "r"(a[1]), "r"(a[2]), "r"(a[3]), "r"(b0), "r"(b1));
}
__device__ __forceinline__ void lds64(u32& a, u32& b, u32 addr) {
    asm("ld.shared.v2.u32 {%0, %1}, [%2];" : "=r"(a), "=r"(b) : "r"(addr));
}
// pack (e0 -> low bf16, e1 -> high); hi = rounded, lo = residual
__device__ __forceinline__ void split_pack(float e0, float e1, u32& hi, u32& lo) {
    u32 h;
    asm("cvt.rn.bf16x2.f32 %0, %1, %2;" : "=r"(h) : "f"(e1), "f"(e0));
    float h0 = __uint_as_float(h << 16);
    float h1 = __uint_as_float(h & 0xffff0000u);
    asm("cvt.rn.bf16x2.f32 %0, %1, %2;" : "=r"(lo) : "f"(e1 - h1), "f"(e0 - h0));
    hi = h;
}
// s[2nt+c] = u^j (1-u)^(24-j) for j = 8nt + 2tg + c; j>24 -> 0. Division-free.
__device__ __forceinline__ void scales8(float u, int tg, float s[8]) {
    float om = 1.0f - u;
    float u2 = u * u, u4 = u2 * u2, u8 = u4 * u4, u16 = u8 * u8;
    float om2 = om * om, om4 = om2 * om2, om8 = om4 * om4, om16 = om8 * om8;
    float ut = ((tg & 1) ? u2 : 1.0f) * ((tg & 2) ? u4 : 1.0f);      // u^{2tg}
    int q = 4 - tg;
    float C0 = ((q & 1) ? om2 : 1.0f) * ((q & 2) ? om4 : 1.0f) * ((q & 4) ? om8 : 1.0f); // om^{8-2tg}
    int r = 3 - tg;
    float C1 = om * ((r & 1) ? om2 : 1.0f) * ((r & 2) ? om4 : 1.0f); // om^{7-2tg}
    float U0 = ut, U1 = ut * u;
    s[0] = U0 * (C0 * om16);
    s[1] = U1 * (C1 * om16);
    s[2] = (U0 * u8) * (C0 * om8);
    s[3] = (U1 * u8) * (C1 * om8);
    s[4] = (U0 * u16) * C0;
    s[5] = (U1 * u16) * C1;
    s[6] = (tg == 0) ? (u16 * u8) : 0.0f;   // j=24 only at tg==0
    s[7] = 0.0f;
}

// ---------------- setup: sc2 ----------------
__global__ void k_sc2() {
    __shared__ double A[25][26];
    __shared__ int piv;
    int t = threadIdx.x;
    if (t < 25) {
        float ti = (float)t / 24.0f, om = 1.0f - ti;
        for (int k = 0; k < 25; k++) {
            float xk = (float)pow((double)ti, (double)k);
            float ym = (float)pow((double)om, (double)(24 - k));
            float val = (xk * ym) * BINC[k];
            A[t][k] = (double)(val * val);
        }
        A[t][25] = 1.0;
    }
    __syncthreads();
    for (int k = 0; k < 25; k++) {
        if (t == 0) {
            int pi = k; double best = fabs(A[k][k]);
            for (int i = k + 1; i < 25; i++) { double v = fabs(A[i][k]); if (v > best) { best = v; pi = i; } }
            piv = pi;
        }
        __syncthreads();
        int pv = piv;
        if (pv != k && t < 26) { double tmp = A[k][t]; A[k][t] = A[pv][t]; A[pv][t] = tmp; }
        __syncthreads();
        if (t < 25 && t != k) {
            double f = A[t][k] / A[k][k];
            for (int j = k; j < 26; j++) A[t][j] -= f * A[k][j];
        }
        __syncthreads();
    }
    if (t < 25) g_sc2[t] = (float)(A[t][25] / A[t][t]);
}

// ---------------- prep: B fragments ----------------
// u16 idx in perm: ((((l*2+path)*2+split)*2+ks)*4+nt)*128 + lane*4 + e
// k = 16ks + 2tg + (e&1) + 8*(e>>1),  j = 8nt + (lane>>2)
__global__ void k_prep_frag(const float* __restrict__ wmr, const float* __restrict__ wvr) {
    int idx = blockIdx.x * blockDim.x + threadIdx.x;
    if (idx >= PPERM * 28672) return;
    int p = idx / 28672;  int r  = idx - p * 28672;
    int l = r / 4096;     int r2 = r - l * 4096;
    int path = r2 / 2048; int r3 = r2 - path * 2048;
    int split = r3 / 1024; int r4 = r3 - split * 1024;
    int ks = r4 / 512;    int r5 = r4 - ks * 512;
    int nt = r5 / 128;    int r6 = r5 - nt * 128;
    int t = r6 / 4,       e = r6 - t * 4;
    int k = 16 * ks + 2 * (t & 3) + (e & 1) + 8 * (e >> 1);
    int j = 8 * nt + (t >> 2);
    float v = 0.0f;
    if (k < 25 && j < 25) {
        int src = ((l * 32 + p) * 25 + k) * 25 + j;
        v = (path == 0) ? wmr[src] * BINC[j]
                        : expf(wvr[src]) * g_sc2[j] * BINC[j] * BINC[j];
    }
    __nv_bfloat16 h = __float2bfloat16(v);
    g_Wf[idx] = (split == 0) ? __bfloat16_as_ushort(h)
                             : __bfloat16_as_ushort(__float2bfloat16(v - __bfloat162float(h)));
}

__global__ void k_prep0(const float* __restrict__ wm0, const float* __restrict__ wv0) {
    int i = blockIdx.x * blockDim.x + threadIdx.x;
    if (i >= PPERM * 25) return;
    int p = i / 25, j = i - p * 25;
    float b = BINC[j];
    float lo = wm0[p * 25 + j] * b;
    float hi = expf(wv0[p * 25 + j]) * g_sc2[j] * b * b;
    g_W0[i] = ((u64)__float_as_uint(hi) << 32) | (u64)__float_as_uint(lo);
}

// ---------------- main: chained HMMA, warp = 16 samples ----------------
__global__ void __launch_bounds__(256, 2) k_main(
    const float* __restrict__ X, const int* __restrict__ perm,
    const float* __restrict__ pprec)
{
    extern __shared__ __align__(16) unsigned short sWf[];   // 57344 B
    __shared__ float2 s0[32];
    __shared__ int sperm[8];

    int p = blockIdx.y;
    int tid = threadIdx.x;
    {
        const float4* src = (const float4*)(g_Wf + (size_t)p * 28672);
        float4* dst = (float4*)sWf;
        #pragma unroll
        for (int i = 0; i < 3584; i += 256) dst[i + tid] = src[i + tid];
    }
    if (tid < 32) s0[tid] = (tid < 25) ? *(const float2*)&g_W0[p * 25 + tid] : make_float2(0.f, 0.f);
    if (tid < 8)  sperm[tid] = perm[p * 8 + tid];
    __syncthreads();

    int lane = tid & 31, w = tid >> 5;
    int tg = lane & 3, g = lane >> 2;
    u32 wbase = (u32)__cvta_generic_to_shared(sWf) + (u32)(lane * 8);
    float invp = 1.0f / __ldg(pprec + p);

    #pragma unroll 1
    for (int tt = 0; tt < 8; tt++) {
        int na = (blockIdx.x * 8 + tt) * 128 + w * 16 + g;   // row g
        int nb = na + 8;                                      // row g+8
        const float* xa = X + na * 8;
        const float* xb = X + nb * 8;

        u32 Amh[2][4], Aml[2][4], Avh[2][4], Avl[2][4];
        float sa[8], sb[8];

        // level 0
        {
            scales8(__ldg(xa + sperm[0]), tg, sa);
            scales8(__ldg(xb + sperm[0]), tg, sb);
            #pragma unroll
            for (int ks = 0; ks < 2; ks++)
            #pragma unroll
            for (int h = 0; h < 2; h++) {
                int nt = 2 * ks + h;
                float2 w0 = s0[8 * nt + 2 * tg];
                float2 w1 = s0[8 * nt + 2 * tg + 1];
                float s0a = sa[2 * nt], s1a = sa[2 * nt + 1];
                float s0b = sb[2 * nt], s1b = sb[2 * nt + 1];
                split_pack(w0.x * s0a, w1.x * s1a, Amh[ks][2 * h],     Aml[ks][2 * h]);
                split_pack(w0.x * s0b, w1.x * s1b, Amh[ks][2 * h + 1], Aml[ks][2 * h + 1]);
                split_pack(w0.y * s0a * s0a, w1.y * s1a * s1a, Avh[ks][2 * h],     Avl[ks][2 * h]);
                split_pack(w0.y * s0b * s0b, w1.y * s1b * s1b, Avh[ks][2 * h + 1], Avl[ks][2 * h + 1]);
            }
        }

        // levels 1..7
        #pragma unroll 1
        for (int l = 1; l <= 7; l++) {
            float Dm[4][4] = {}, Dv[4][4] = {};
            u32 lb = wbase + (u32)((l - 1) * 8192);
            #pragma unroll
            for (int nt = 0; nt < 4; nt++) {
                u32 o = lb + (u32)(nt * 256);
                u32 h00, h01, h10, h11, l00, l01, l10, l11;
                lds64(h00, h01, o);           lds64(h10, h11, o + 1024);
                lds64(l00, l01, o + 2048);    lds64(l10, l11, o + 3072);
                mma16816(Dm[nt], Amh[0], h00, h01);
                mma16816(Dm[nt], Amh[1], h10, h11);
                mma16816(Dm[nt], Amh[0], l00, l01);
                mma16816(Dm[nt], Amh[1], l10, l11);
                mma16816(Dm[nt], Aml[0], h00, h01);
                mma16816(Dm[nt], Aml[1], h10, h11);
                lds64(h00, h01, o + 4096);    lds64(h10, h11, o + 5120);
                lds64(l00, l01, o + 6144);    lds64(l10, l11, o + 7168);
                mma16816(Dv[nt], Avh[0], h00, h01);
                mma16816(Dv[nt], Avh[1], h10, h11);
                mma16816(Dv[nt], Avh[0], l00, l01);
                mma16816(Dv[nt], Avh[1], l10, l11);
                mma16816(Dv[nt], Avl[0], h00, h01);
                mma16816(Dv[nt], Avl[1], h10, h11);
            }
            scales8(__ldg(xa + sperm[l]), tg, sa);
            scales8(__ldg(xb + sperm[l]), tg, sb);
            if (l < 7) {
                #pragma unroll
                for (int ks = 0; ks < 2; ks++)
                #pragma unroll
                for (int h = 0; h < 2; h++) {
                    int nt = 2 * ks + h;
                    float s0a = sa[2 * nt], s1a = sa[2 * nt + 1];
                    float s0b = sb[2 * nt], s1b = sb[2 * nt + 1];
                    split_pack(Dm[nt][0] * s0a, Dm[nt][1] * s1a, Amh[ks][2 * h],     Aml[ks][2 * h]);
                    split_pack(Dm[nt][2] * s0b, Dm[nt][3] * s1b, Amh[ks][2 * h + 1], Aml[ks][2 * h + 1]);
                    split_pack(Dv[nt][0] * s0a * s0a, Dv[nt][1] * s1a * s1a, Avh[ks][2 * h],     Avl[ks][2 * h]);
                    split_pack(Dv[nt][2] * s0b * s0b, Dv[nt][3] * s1b * s1b, Avh[ks][2 * h + 1], Avl[ks][2 * h + 1]);
                }
            } else {
                float smA = 0.f, smB = 0.f, svA = 0.f, svB = 0.f;
                #pragma unroll
                for (int nt = 0; nt < 4; nt++) {
                    float s0a = sa[2 * nt], s1a = sa[2 * nt + 1];
                    float s0b = sb[2 * nt], s1b = sb[2 * nt + 1];
                    smA += Dm[nt][0] * s0a + Dm[nt][1] * s1a;
                    smB += Dm[nt][2] * s0b + Dm[nt][3] * s1b;
                    svA += Dv[nt][0] * (s0a * s0a) + Dv[nt][1] * (s1a * s1a);
                    svB += Dv[nt][2] * (s0b * s0b) + Dv[nt][3] * (s1b * s1b);
                }
                smA += __shfl_xor_sync(0xffffffff, smA, 1); smA += __shfl_xor_sync(0xffffffff, smA, 2);
                smB += __shfl_xor_sync(0xffffffff, smB, 1); smB += __shfl_xor_sync(0xffffffff, smB, 2);
                svA += __shfl_xor_sync(0xffffffff, svA, 1); svA += __shfl_xor_sync(0xffffffff, svA, 2);
                svB += __shfl_xor_sync(0xffffffff, svB, 1); svB += __shfl_xor_sync(0xffffffff, svB, 2);
                if (tg == 0) {
                    g_pm[p * NSAMP + na] = smA;
                    g_pv[p * NSAMP + na] = svA * invp;
                    g_pm[p * NSAMP + nb] = smB;
                    g_pv[p * NSAMP + nb] = svB * invp;
                }
            }
        }
    }
}

// ---------------- reduction over permutations ----------------
__global__ void k_reduce(float* __restrict__ out) {
    int n = blockIdx.x * blockDim.x + threadIdx.x;
    float sm = 0.f, sv = 0.f;
    #pragma unroll
    for (int p = 0; p < PPERM; p++) {
        sm += g_pm[p * NSAMP + n];
        sv += g_pv[p * NSAMP + n];
    }
    out[2 * n]     = sm;
    out[2 * n + 1] = sv;
}

extern "C" void kernel_launch(void* const* d_in, const int* in_sizes, int n_in,
                              void* d_out, int out_size) {
    const float* X    = (const float*)d_in[0];
    const int*   perm = (const int*)  d_in[1];
    const float* wm0  = (const float*)d_in[2];
    const float* wmr  = (const float*)d_in[3];
    const float* wv0  = (const float*)d_in[4];
    const float* wvr  = (const float*)d_in[5];
    const float* pp   = (const float*)d_in[6];

    cudaFuncSetAttribute(k_main, cudaFuncAttributeMaxDynamicSharedMemorySize, 57344);
    // launch index 3 = k_main (ncu captures the 4th launch)
    k_sc2<<<1, 32>>>();
    k_prep_frag<<<(PPERM * 28672 + 255) / 256, 256>>>(wmr, wvr);
    k_prep0<<<(PPERM * 25 + 255) / 256, 256>>>(wm0, wv0);
    k_main<<<dim3(32, 32), 256, 57344>>>(X, perm, pp);
    k_reduce<<<NSAMP / 256, 256>>>((float*)d_out);
}